// round 16
// baseline (speedup 1.0000x reference)
#include <cuda_runtime.h>
#include <cstdint>

// out[p] = (L >= 0) || (missing(p) - L >= 0.5), written as float 0.0/1.0
// L = 7-point Laplacian (6*center - face neighbors, zero padding);
// missing(p) = count of out-of-grid face neighbors (kernel sums to 0, so
// conv(1-m,k) = missing(p) - conv(m,k)).
//
// R15 (rolling-z x-quad, KZ=16 single wave, __stcs, shuffle x-halo,
// hoisted thresholds) with PREFETCH DISTANCE 2: the z+1-plane load issued
// at iteration iz is consumed at iz+2, hiding the ~250-cycle L2 latency
// behind two iteration bodies instead of one.

#define DSZ 192
#define KZ  16
#define ZT  (DSZ / KZ)   // 12 z-tiles

__global__ __launch_bounds__(384, 4) void mask_kernel(
    const float* __restrict__ m, float* __restrict__ out)
{
    const int tx = threadIdx.x;                       // 0..47 -> x quad
    const int y  = blockIdx.y * blockDim.y + threadIdx.y;
    const int zb = blockIdx.z;
    const int z0 = (zb % ZT) * KZ;
    const int b  = zb / ZT;
    const int x0 = tx * 4;
    const int lane = (threadIdx.y * 48 + tx) & 31;

    const size_t plane = (size_t)DSZ * DSZ;
    const float* p = m + (((size_t)b * DSZ + z0) * DSZ + y) * DSZ + x0;
    float* q = out + (((size_t)b * DSZ + z0) * DSZ + y) * DSZ + x0;

    const float4 zero4 = make_float4(0.f, 0.f, 0.f, 0.f);
    const bool hasYm = (y > 0);
    const bool hasYp = (y < DSZ - 1);
    const bool hasXl = (x0 > 0);
    const bool hasXr = (x0 + 4 < DSZ);
    const bool edgeL = hasXl && (lane == 0);
    const bool edgeR = hasXr && (lane == 31);

    // interior-z thresholds, precomputed once
    const float missY = (float)((int)(!hasYm) + (int)(!hasYp));
    const float f0i = missY + (float)(int)(!hasXl);
    const float fmi = missY;
    const float f3i = missY + (float)(int)(!hasXr);
    // z-boundary bumps (applied only at iz==0 / iz==KZ-1)
    const float mzFirst = (z0 == 0)        ? 1.f : 0.f;
    const float mzLast  = (z0 == DSZ - KZ) ? 1.f : 0.f;

    float4 A  = (z0 > 0) ? *(const float4*)(p - plane) : zero4;       // z-1
    float4 B  = *(const float4*)(p);                                   // z
    float4 C  = *(const float4*)(p + plane);                           // z+1
    float4 C2 = (z0 + 2 < DSZ) ? *(const float4*)(p + 2 * plane) : zero4; // z+2

    #pragma unroll
    for (int iz = 0; iz < KZ; ++iz) {
        // prefetch plane z+3 (consumed two iterations from now)
        float4 Cn = zero4;
        if (iz < KZ - 2) {
            if (z0 + iz + 3 < DSZ) Cn = *(const float4*)(p + 3 * plane);
        }

        float4 ym = hasYm ? *(const float4*)(p - DSZ) : zero4;
        float4 yp = hasYp ? *(const float4*)(p + DSZ) : zero4;

        // x-halo via shuffle of the rolling center row
        float xls = __shfl_up_sync(0xffffffffu, B.w, 1);
        float xrs = __shfl_down_sync(0xffffffffu, B.x, 1);
        float xl = 0.f, xr = 0.f;
        if (hasXl) xl = edgeL ? __ldg(p - 1) : xls;
        if (hasXr) xr = edgeR ? __ldg(p + 4) : xrs;

        float L0 = 6.f * B.x - (xl  + B.y + ym.x + yp.x + A.x + C.x);
        float L1 = 6.f * B.y - (B.x + B.z + ym.y + yp.y + A.y + C.y);
        float L2 = 6.f * B.z - (B.y + B.w + ym.z + yp.z + A.z + C.z);
        float L3 = 6.f * B.w - (B.z + xr  + ym.w + yp.w + A.w + C.w);

        // compile-time folded for interior iterations (mzv == 0.0f constant)
        const float mzv = (iz == 0) ? mzFirst : ((iz == KZ - 1) ? mzLast : 0.f);
        const float f0 = f0i + mzv;
        const float fm = fmi + mzv;
        const float f3 = f3i + mzv;

        float4 o;
        o.x = ((L0 >= 0.f) || (f0 - L0 >= 0.5f)) ? 1.f : 0.f;
        o.y = ((L1 >= 0.f) || (fm - L1 >= 0.5f)) ? 1.f : 0.f;
        o.z = ((L2 >= 0.f) || (fm - L2 >= 0.5f)) ? 1.f : 0.f;
        o.w = ((L3 >= 0.f) || (f3 - L3 >= 0.5f)) ? 1.f : 0.f;

        __stcs((float4*)q, o);

        A = B; B = C; C = C2; C2 = Cn;
        p += plane; q += plane;
    }
}

extern "C" void kernel_launch(void* const* d_in, const int* in_sizes, int n_in,
                              void* d_out, int out_size)
{
    const float* m = (const float*)d_in[0];
    float* out = (float*)d_out;

    dim3 block(48, 8, 1);                 // 384 threads: full row x 8 rows
    dim3 grid(1, DSZ / 8, 2 * ZT);        // y-tiles, (batch * z-tiles) = 576
    mask_kernel<<<grid, block>>>(m, out);
}

// round 17
// speedup vs baseline: 1.0808x; 1.0808x over previous
#include <cuda_runtime.h>
#include <cstdint>

// out[p] = (L >= 0) || (missing(p) - L >= 0.5), written as float 0.0/1.0
// L = 7-point Laplacian (6*center - face neighbors, zero padding);
// missing(p) = count of out-of-grid face neighbors (kernel sums to 0, so
// conv(1-m,k) = missing(p) - conv(m,k)).
//
// R15 (rolling-z x-quad, KZ=16 single wave, __stcs, 1-deep C prefetch,
// hoisted thresholds) + PIPELINED X-HALO: next iteration's xl/xr are
// computed from C (already arrived) during the current iteration, so the
// SHFL no longer sits on the B<-C critical path. +2 regs only.

#define DSZ 192
#define KZ  16
#define ZT  (DSZ / KZ)   // 12 z-tiles

__global__ __launch_bounds__(384, 4) void mask_kernel(
    const float* __restrict__ m, float* __restrict__ out)
{
    const int tx = threadIdx.x;                       // 0..47 -> x quad
    const int y  = blockIdx.y * blockDim.y + threadIdx.y;
    const int zb = blockIdx.z;
    const int z0 = (zb % ZT) * KZ;
    const int b  = zb / ZT;
    const int x0 = tx * 4;
    const int lane = (threadIdx.y * 48 + tx) & 31;

    const size_t plane = (size_t)DSZ * DSZ;
    const float* p = m + (((size_t)b * DSZ + z0) * DSZ + y) * DSZ + x0;
    float* q = out + (((size_t)b * DSZ + z0) * DSZ + y) * DSZ + x0;

    const float4 zero4 = make_float4(0.f, 0.f, 0.f, 0.f);
    const bool hasYm = (y > 0);
    const bool hasYp = (y < DSZ - 1);
    const bool hasXl = (x0 > 0);
    const bool hasXr = (x0 + 4 < DSZ);
    const bool edgeL = hasXl && (lane == 0);
    const bool edgeR = hasXr && (lane == 31);

    // interior-z thresholds, precomputed once
    const float missY = (float)((int)(!hasYm) + (int)(!hasYp));
    const float f0i = missY + (float)(int)(!hasXl);
    const float fmi = missY;
    const float f3i = missY + (float)(int)(!hasXr);
    const float mzFirst = (z0 == 0)        ? 1.f : 0.f;
    const float mzLast  = (z0 == DSZ - KZ) ? 1.f : 0.f;

    float4 A = (z0 > 0) ? *(const float4*)(p - plane) : zero4;  // z-1
    float4 B = *(const float4*)(p);                              // z
    float4 C = *(const float4*)(p + plane);                      // z+1 (in-grid)

    // x-halo for the FIRST iteration, from B
    float xl, xr;
    {
        float xls = __shfl_up_sync(0xffffffffu, B.w, 1);
        float xrs = __shfl_down_sync(0xffffffffu, B.x, 1);
        xl = hasXl ? (edgeL ? __ldg(p - 1) : xls) : 0.f;
        xr = hasXr ? (edgeR ? __ldg(p + 4) : xrs) : 0.f;
    }

    #pragma unroll
    for (int iz = 0; iz < KZ; ++iz) {
        // prefetch C for the NEXT iteration (plane z+2)
        float4 Cn = zero4;
        if (iz < KZ - 1) {
            if (z0 + iz + 2 < DSZ) Cn = *(const float4*)(p + 2 * plane);
        }

        float4 ym = hasYm ? *(const float4*)(p - DSZ) : zero4;
        float4 yp = hasYp ? *(const float4*)(p + DSZ) : zero4;

        // NEXT iteration's x-halo from C (already resident) — off the
        // critical path of this iteration's compute.
        float xln = 0.f, xrn = 0.f;
        if (iz < KZ - 1) {
            const bool hasZp = (z0 + iz + 1 < DSZ);   // C in-grid (always true here except last tile edge)
            float xlsn = __shfl_up_sync(0xffffffffu, C.w, 1);
            float xrsn = __shfl_down_sync(0xffffffffu, C.x, 1);
            if (hasXl) xln = (edgeL && hasZp) ? __ldg(p + plane - 1) : (edgeL ? 0.f : xlsn);
            if (hasXr) xrn = (edgeR && hasZp) ? __ldg(p + plane + 4) : (edgeR ? 0.f : xrsn);
        }

        float L0 = 6.f * B.x - (xl  + B.y + ym.x + yp.x + A.x + C.x);
        float L1 = 6.f * B.y - (B.x + B.z + ym.y + yp.y + A.y + C.y);
        float L2 = 6.f * B.z - (B.y + B.w + ym.z + yp.z + A.z + C.z);
        float L3 = 6.f * B.w - (B.z + xr  + ym.w + yp.w + A.w + C.w);

        const float mzv = (iz == 0) ? mzFirst : ((iz == KZ - 1) ? mzLast : 0.f);
        const float f0 = f0i + mzv;
        const float fm = fmi + mzv;
        const float f3 = f3i + mzv;

        float4 o;
        o.x = ((L0 >= 0.f) || (f0 - L0 >= 0.5f)) ? 1.f : 0.f;
        o.y = ((L1 >= 0.f) || (fm - L1 >= 0.5f)) ? 1.f : 0.f;
        o.z = ((L2 >= 0.f) || (fm - L2 >= 0.5f)) ? 1.f : 0.f;
        o.w = ((L3 >= 0.f) || (f3 - L3 >= 0.5f)) ? 1.f : 0.f;

        __stcs((float4*)q, o);

        A = B; B = C; C = Cn;
        xl = xln; xr = xrn;
        p += plane; q += plane;
    }
}

extern "C" void kernel_launch(void* const* d_in, const int* in_sizes, int n_in,
                              void* d_out, int out_size)
{
    const float* m = (const float*)d_in[0];
    float* out = (float*)d_out;

    dim3 block(48, 8, 1);                 // 384 threads: full row x 8 rows
    dim3 grid(1, DSZ / 8, 2 * ZT);        // y-tiles, (batch * z-tiles) = 576
    mask_kernel<<<grid, block>>>(m, out);
}